// round 15
// baseline (speedup 1.0000x reference)
#include <cuda_runtime.h>
#include <cstdint>
#include <cstdio>

// ---------------------------------------------------------------------------
// Problem constants
// ---------------------------------------------------------------------------
#define B_    4
#define S_    4096
#define C_    1280
#define X_    2048
#define T_    77
#define LID_  32
#define H_    20
#define D_    64

#define M_BIG (B_ * S_)        // 16384

// ---------------------------------------------------------------------------
// Scratch (no allocations allowed -> __device__ globals)
// ---------------------------------------------------------------------------
__device__ float g_q   [(size_t)M_BIG * C_];
__device__ float g_comb[(size_t)M_BIG * C_];     // pre-rounded to tf32
__device__ float g_k [B_ * T_   * C_];
__device__ float g_v [B_ * T_   * C_];
__device__ float g_ik[B_ * LID_ * C_];
__device__ float g_iv[B_ * LID_ * C_];

// tf32-pre-rounded operand copies
__device__ float g_hid_t[(size_t)M_BIG * C_];
__device__ float g_enc_t[B_ * T_   * X_];
__device__ float g_idt  [B_ * LID_ * X_];
__device__ float g_wq_t [C_ * C_];
__device__ float g_wk_t [C_ * X_];
__device__ float g_wv_t [C_ * X_];
__device__ float g_wik_t[C_ * X_];
__device__ float g_wiv_t[C_ * X_];
__device__ float g_wo_t [C_ * C_];

__device__ __forceinline__ uint32_t f2tf32(float x) {
    uint32_t r;
    asm("cvt.rna.tf32.f32 %0, %1;" : "=r"(r) : "f"(x));
    return r;
}
__device__ __forceinline__ float roundtf(float x) {
    return __uint_as_float(f2tf32(x));
}

// ---------------------------------------------------------------------------
// Pre-round pass
// ---------------------------------------------------------------------------
__global__ __launch_bounds__(256)
void round_multi(const float* __restrict__ hidden, const float* __restrict__ enc,
                 const float* __restrict__ idemb,
                 const float* __restrict__ Wq, const float* __restrict__ Wk,
                 const float* __restrict__ Wv, const float* __restrict__ Wik,
                 const float* __restrict__ Wiv, const float* __restrict__ Wo,
                 float* hid_t, float* enc_t, float* id_t,
                 float* wq_t, float* wk_t, float* wv_t,
                 float* wik_t, float* wiv_t, float* wo_t)
{
    const float* src; float* dst; size_t n;
    switch (blockIdx.y) {
        case 0: src = hidden; dst = hid_t; n = (size_t)M_BIG * C_;   break;
        case 1: src = enc;    dst = enc_t; n = (size_t)B_ * T_ * X_; break;
        case 2: src = idemb;  dst = id_t;  n = (size_t)B_ * LID_ * X_; break;
        case 3: src = Wq;     dst = wq_t;  n = (size_t)C_ * C_;      break;
        case 4: src = Wk;     dst = wk_t;  n = (size_t)C_ * X_;      break;
        case 5: src = Wv;     dst = wv_t;  n = (size_t)C_ * X_;      break;
        case 6: src = Wik;    dst = wik_t; n = (size_t)C_ * X_;      break;
        case 7: src = Wiv;    dst = wiv_t; n = (size_t)C_ * X_;      break;
        default:src = Wo;     dst = wo_t;  n = (size_t)C_ * C_;      break;
    }
    size_t n4 = n >> 2;
    size_t stride = (size_t)gridDim.x * blockDim.x;
    for (size_t i = (size_t)blockIdx.x * blockDim.x + threadIdx.x; i < n4; i += stride) {
        float4 v = ((const float4*)src)[i];
        v.x = roundtf(v.x); v.y = roundtf(v.y);
        v.z = roundtf(v.z); v.w = roundtf(v.w);
        ((float4*)dst)[i] = v;
    }
}

// ---------------------------------------------------------------------------
// cp.async helpers
// ---------------------------------------------------------------------------
__device__ __forceinline__ void cp_async16(uint32_t dst, const void* src) {
    asm volatile("cp.async.cg.shared.global [%0], [%1], 16;\n"
                 :: "r"(dst), "l"(src));
}
__device__ __forceinline__ void cp_commit() {
    asm volatile("cp.async.commit_group;\n");
}
template <int N>
__device__ __forceinline__ void cp_wait() {
    asm volatile("cp.async.wait_group %0;\n" :: "n"(N));
}

__device__ __forceinline__ void mma_tf32(float* c, const uint32_t* a, const uint32_t* b) {
    asm volatile(
        "mma.sync.aligned.m16n8k8.row.col.f32.tf32.tf32.f32 "
        "{%0,%1,%2,%3}, {%4,%5,%6,%7}, {%8,%9}, {%0,%1,%2,%3};\n"
        : "+f"(c[0]), "+f"(c[1]), "+f"(c[2]), "+f"(c[3])
        : "r"(a[0]), "r"(a[1]), "r"(a[2]), "r"(a[3]),
          "r"(b[0]), "r"(b[1]));
}

// ---------------------------------------------------------------------------
// mma.sync tf32 GEMM (NT): C[m,n] = sum_k A[m,k]*B[n,k]
// R12/R14 configuration: block 128x128, BK=32, 4 warps (warp tile 64x64),
// GLD=36 padded smem, 3-stage cp.async, 2 CTAs/SM.
// ---------------------------------------------------------------------------
#define GT   128                    // threads per block
#define GBM 128
#define GBN 128
#define GBK 32
#define GLD 36
#define ASZ (GBM * GLD)
#define BSZ (GBN * GLD)
#define STG (ASZ + BSZ)
#define NSTG 3
#define GEMM_SMEM_BYTES (NSTG * STG * 4)     // 110592 (x2 CTAs = 221184 <= 228KB)

template <bool EPI, bool CLAMP>
__device__ __forceinline__
void gemm_body(const float* __restrict__ A, const float* __restrict__ Bm,
               float* __restrict__ C, int M, int K, int row0, int col0,
               const float* __restrict__ bias, const float* __restrict__ residual,
               float* smem)
{
    const int tid  = threadIdx.x;
    const int lane = tid & 31;
    const int w    = tid >> 5;
    const int gid  = lane >> 2;
    const int tig  = lane & 3;
    const int wm   = (w & 1) * 64;
    const int wn   = (w >> 1) * 64;

    uint32_t smem_u32 = (uint32_t)__cvta_generic_to_shared(smem);

    float acc[4][8][4];
    #pragma unroll
    for (int mf = 0; mf < 4; mf++)
        #pragma unroll
        for (int nf = 0; nf < 8; nf++)
            #pragma unroll
            for (int r = 0; r < 4; r++) acc[mf][nf][r] = 0.f;

    const int niter = K / GBK;

    auto load_tile = [&](int kt, int st) {
        const int k0 = kt * GBK;
        uint32_t abase = smem_u32 + (uint32_t)(st * STG) * 4u;
        uint32_t bbase = abase + (uint32_t)ASZ * 4u;
        #pragma unroll
        for (int i = 0; i < 8; i++) {
            int idx = tid + i * GT;
            int m   = idx >> 3;
            int k4  = idx & 7;
            int gr  = row0 + m;
            if (CLAMP) { if (gr > M - 1) gr = M - 1; }
            cp_async16(abase + (uint32_t)(m * GLD + k4 * 4) * 4u,
                       A + (size_t)gr * K + k0 + k4 * 4);
        }
        #pragma unroll
        for (int i = 0; i < 8; i++) {
            int idx = tid + i * GT;
            int n   = idx >> 3;
            int k4  = idx & 7;
            cp_async16(bbase + (uint32_t)(n * GLD + k4 * 4) * 4u,
                       Bm + (size_t)(col0 + n) * K + k0 + k4 * 4);
        }
        cp_commit();
    };

    load_tile(0, 0);
    load_tile(1, 1);

    for (int it = 0; it < niter; ++it) {
        if (it + 1 < niter) cp_wait<1>(); else cp_wait<0>();
        __syncthreads();
        if (it + 2 < niter) load_tile(it + 2, (it + 2) % NSTG);

        const uint32_t* As = (const uint32_t*)(smem + (it % NSTG) * STG);
        const uint32_t* Bs = As + ASZ;

        #pragma unroll
        for (int kk = 0; kk < GBK; kk += 8) {
            uint32_t a[4][4], bf[8][2];
            #pragma unroll
            for (int mf = 0; mf < 4; mf++) {
                int mb2 = wm + mf * 16;
                a[mf][0] = As[(mb2 + gid)     * GLD + kk + tig];
                a[mf][1] = As[(mb2 + gid + 8) * GLD + kk + tig];
                a[mf][2] = As[(mb2 + gid)     * GLD + kk + tig + 4];
                a[mf][3] = As[(mb2 + gid + 8) * GLD + kk + tig + 4];
            }
            #pragma unroll
            for (int nf = 0; nf < 8; nf++) {
                int nb = wn + nf * 8;
                bf[nf][0] = Bs[(nb + gid) * GLD + kk + tig];
                bf[nf][1] = Bs[(nb + gid) * GLD + kk + tig + 4];
            }
            #pragma unroll
            for (int mf = 0; mf < 4; mf++)
                #pragma unroll
                for (int nf = 0; nf < 8; nf++)
                    mma_tf32(acc[mf][nf], a[mf], bf[nf]);
        }
    }

    #pragma unroll
    for (int mf = 0; mf < 4; mf++) {
        int r0g = row0 + wm + mf * 16 + gid;
        int r1g = r0g + 8;
        #pragma unroll
        for (int nf = 0; nf < 8; nf++) {
            int gc = col0 + wn + nf * 8 + tig * 2;
            float2 v0 = make_float2(acc[mf][nf][0], acc[mf][nf][1]);
            float2 v1 = make_float2(acc[mf][nf][2], acc[mf][nf][3]);
            if (EPI) {
                float2 bb = *(const float2*)(bias + gc);
                v0.x += bb.x; v0.y += bb.y;
                v1.x += bb.x; v1.y += bb.y;
            }
            if (r0g < M) {
                if (EPI) {
                    float2 rr = *(const float2*)(residual + (size_t)r0g * C_ + gc);
                    v0.x += rr.x; v0.y += rr.y;
                }
                *(float2*)(C + (size_t)r0g * C_ + gc) = v0;
            }
            if (r1g < M) {
                if (EPI) {
                    float2 rr = *(const float2*)(residual + (size_t)r1g * C_ + gc);
                    v1.x += rr.x; v1.y += rr.y;
                }
                *(float2*)(C + (size_t)r1g * C_ + gc) = v1;
            }
        }
    }
}

// Q projection + all four K/V projections in ONE launch. grid (10, 136).
// KV blocks (K=2048, 1.6x longer) scheduled FIRST to avoid a long tail.
__global__ __launch_bounds__(GT, 2)
void gemm_main(const float* __restrict__ hid, const float* __restrict__ wq,
               float* __restrict__ q,
               const float* __restrict__ enc, const float* __restrict__ idemb,
               const float* __restrict__ wk,  const float* __restrict__ wv,
               const float* __restrict__ wik, const float* __restrict__ wiv,
               float* __restrict__ k, float* __restrict__ v,
               float* __restrict__ ik, float* __restrict__ iv)
{
    extern __shared__ float dynsm[];
    const int y = blockIdx.y;
    const int col0 = blockIdx.x * GBN;
    if (y >= 8) {
        gemm_body<false, false>(hid, wq, q, M_BIG, C_, (y - 8) * GBM, col0,
                                nullptr, nullptr, dynsm);
        return;
    }
    const int z = y;
    const float* A; const float* Bm; float* Cp; int M; int row0;
    if (z < 3)       { A = enc;   Bm = wk;  Cp = k;  M = B_ * T_;   row0 = z * GBM; }
    else if (z < 6)  { A = enc;   Bm = wv;  Cp = v;  M = B_ * T_;   row0 = (z - 3) * GBM; }
    else if (z == 6) { A = idemb; Bm = wik; Cp = ik; M = B_ * LID_; row0 = 0; }
    else             { A = idemb; Bm = wiv; Cp = iv; M = B_ * LID_; row0 = 0; }
    gemm_body<false, true>(A, Bm, Cp, M, X_, row0, col0, nullptr, nullptr, dynsm);
}

// O projection + bias + residual. grid (10, 128).
__global__ __launch_bounds__(GT, 2)
void gemm_epi(const float* __restrict__ A, const float* __restrict__ W,
              float* __restrict__ C,
              const float* __restrict__ bias, const float* __restrict__ residual)
{
    extern __shared__ float dynsm[];
    gemm_body<true, false>(A, W, C, M_BIG, C_, blockIdx.y * GBM,
                           blockIdx.x * GBN, bias, residual, dynsm);
}

// ---------------------------------------------------------------------------
// Tensor-core attention (tf32 mma).
// Per CTA: 128 queries x one (b,h). Combined key axis 128:
//   cols 0..76  = cross keys (K, V)
//   cols 77..108= id keys   (idK, idV)
//   cols 109..127 = padding (e forced to 0)
// One score GEMM [128x64]x[64x128], dual softmax via column classification
// (P normalized per-row by matching denominator BEFORE PV), one PV GEMM
// [128x128]x[128x64] with concatenated V -> cross_out + id_out in one acc.
// ---------------------------------------------------------------------------
#define AQ   128                    // queries per CTA
#define NK   128                    // padded key axis
#define NKR  109                    // real keys (77 cross + 32 id)
#define QLD  68                     // Qs/Ks row stride (64 + 4)
#define PLD  132                    // P/Vt key-dim stride (128 + 4)

#define SM_QS  (AQ * QLD)           // 8704
#define SM_KS  (NK * QLD)           // 8704
#define SM_VT  (D_ * PLD)           // 8448
#define SM_P   (AQ * PLD)           // 16896
#define SM_PS  (4 * AQ * 2)         // 1024 (psum[nwarp][row][cls])
#define SM_ID  (AQ * 2)             // 256  (invden[row][cls])
#define ATTN_SMEM_FLOATS (SM_QS + SM_KS + SM_VT + SM_P + SM_PS + SM_ID)
#define ATTN_SMEM_BYTES  (ATTN_SMEM_FLOATS * 4)   // 176128

__global__ __launch_bounds__(256, 1)
void attn_kernel(const float* __restrict__ q,
                 const float* __restrict__ kbuf, const float* __restrict__ vbuf,
                 const float* __restrict__ ikbuf, const float* __restrict__ ivbuf,
                 float* __restrict__ out)
{
    extern __shared__ float sm[];
    float* Qs   = sm;
    float* Ks   = Qs + SM_QS;
    float* Vt   = Ks + SM_KS;
    float* P    = Vt + SM_VT;
    float* psum = P  + SM_P;
    float* invd = psum + SM_PS;

    const int bh = blockIdx.y;
    const int b = bh / H_, h = bh % H_;
    const int s0 = blockIdx.x * AQ;
    const int tid = threadIdx.x, lane = tid & 31, w = tid >> 5;
    const int gid = lane >> 2, tig = lane & 3;
    const float scale = 0.125f;

    // ---- stage: Q (rounded) ----
    for (int idx = tid; idx < AQ * 16; idx += 256) {
        int r = idx >> 4, d4 = (idx & 15) << 2;
        float4 g = *(const float4*)(q + ((size_t)b * S_ + s0 + r) * C_ + h * D_ + d4);
        float* dst = Qs + r * QLD + d4;
        dst[0] = roundtf(g.x); dst[1] = roundtf(g.y);
        dst[2] = roundtf(g.z); dst[3] = roundtf(g.w);
    }
    // ---- stage: K rows 0..76 (cross), 77..108 (id) ----
    for (int idx = tid; idx < T_ * 16; idx += 256) {
        int r = idx >> 4, d4 = (idx & 15) << 2;
        float4 g = *(const float4*)(kbuf + ((size_t)b * T_ + r) * C_ + h * D_ + d4);
        float* dst = Ks + r * QLD + d4;
        dst[0] = roundtf(g.x); dst[1] = roundtf(g.y);
        dst[2] = roundtf(g.z); dst[3] = roundtf(g.w);
    }
    for (int idx = tid; idx < LID_ * 16; idx += 256) {
        int r = idx >> 4, d4 = (idx & 15) << 2;
        float4 g = *(const float4*)(ikbuf + ((size_t)b * LID_ + r) * C_ + h * D_ + d4);
        float* dst = Ks + (T_ + r) * QLD + d4;
        dst[0] = roundtf(g.x); dst[1] = roundtf(g.y);
        dst[2] = roundtf(g.z); dst[3] = roundtf(g.w);
    }
    // ---- stage: Vt (transposed, zero-padded key cols) ----
    for (int idx = tid; idx < SM_VT; idx += 256) Vt[idx] = 0.f;
    __syncthreads();   // zeros visible before transpose-fill
    for (int idx = tid; idx < T_ * 16; idx += 256) {
        int r = idx >> 4, d4 = (idx & 15) << 2;
        float4 g = *(const float4*)(vbuf + ((size_t)b * T_ + r) * C_ + h * D_ + d4);
        Vt[(d4 + 0) * PLD + r] = roundtf(g.x);
        Vt[(d4 + 1) * PLD + r] = roundtf(g.y);
        Vt[(d4 + 2) * PLD + r] = roundtf(g.z);
        Vt[(d4 + 3) * PLD + r] = roundtf(g.w);
    }
    for (int idx = tid; idx < LID_ * 16; idx += 256) {
        int r = idx >> 4, d4 = (idx & 15) << 2;
        float4 g = *(const float4*)(ivbuf + ((size_t)b * LID_ + r) * C_ + h * D_ + d4);
        Vt[(d4 + 0) * PLD + T_ + r] = roundtf(g.x);
        Vt[(d4 + 1) * PLD + T_ + r] = roundtf(g.y);
        Vt[(d4 + 2) * PLD + T_ + r] = roundtf(g.z);
        Vt[(d4 + 3) * PLD + T_ + r] = roundtf(g.w);
    }
    __syncthreads();

    // ---- score GEMM: S[128 q][128 key] ; warp grid 2(m) x 4(n) ----
    const int wm = (w & 1) * 64;
    const int wn = (w >> 1) * 32;
    const uint32_t* Qu = (const uint32_t*)Qs;
    const uint32_t* Ku = (const uint32_t*)Ks;

    float sacc[4][4][4];
    #pragma unroll
    for (int mf = 0; mf < 4; mf++)
        #pragma unroll
        for (int nf = 0; nf < 4; nf++)
            #pragma unroll
            for (int r = 0; r < 4; r++) sacc[mf][nf][r] = 0.f;

    #pragma unroll
    for (int kk = 0; kk < D_; kk += 8) {
        uint32_t a[4][4], bf[4][2];
        #pragma unroll
        for (int mf = 0; mf < 4; mf++) {
            int mb2 = wm + mf * 16;
            a[mf][0] = Qu[(mb2 + gid)     * QLD + kk + tig];
            a[mf][1] = Qu[(mb2 + gid + 8) * QLD + kk + tig];
            a[mf][2] = Qu[(mb2 + gid)     * QLD + kk + tig + 4];
            a[mf][3] = Qu[(mb2 + gid + 8) * QLD + kk + tig + 4];
        }
        #pragma unroll
        for (int nf = 0; nf < 4; nf++) {
            int nb = wn + nf * 8;
            bf[nf][0] = Ku[(nb + gid) * QLD + kk + tig];
            bf[nf][1] = Ku[(nb + gid) * QLD + kk + tig + 4];
        }
        #pragma unroll
        for (int mf = 0; mf < 4; mf++)
            #pragma unroll
            for (int nf = 0; nf < 4; nf++)
                mma_tf32(sacc[mf][nf], a[mf], bf[nf]);
    }

    // ---- exp + per-class row sums (no max shift; scores O(1)) ----
    float sums[4][2][2];
    #pragma unroll
    for (int mf = 0; mf < 4; mf++)
        #pragma unroll
        for (int r = 0; r < 2; r++) { sums[mf][r][0] = 0.f; sums[mf][r][1] = 0.f; }

    #pragma unroll
    for (int mf = 0; mf < 4; mf++)
        #pragma unroll
        for (int nf = 0; nf < 4; nf++) {
            int col0 = wn + nf * 8 + tig * 2;
            int col1 = col0 + 1;
            #pragma unroll
            for (int r = 0; r < 2; r++) {
                float e0 = (col0 < NKR) ? __expf(sacc[mf][nf][r * 2 + 0] * scale) : 0.f;
                float e1 = (col1 < NKR) ? __expf(sacc[mf][nf][r * 2 + 1] * scale) : 0.f;
                if (col0 < T_) sums[mf][r][0] += e0; else sums[mf][r][1] += e0;
                if (col1 < T_) sums[mf][r][0] += e1; else sums[mf][r][1] += e1;
                sacc[mf][nf][r * 2 + 0] = e0;
                sacc[mf][nf][r * 2 + 1] = e1;
            }
        }

    // quad-reduce (tig lanes share rows) and publish partials
    #pragma unroll
    for (int mf = 0; mf < 4; mf++)
        #pragma unroll
        for (int r = 0; r < 2; r++)
            #pragma unroll
            for (int cls = 0; cls < 2; cls++) {
                float s = sums[mf][r][cls];
                s += __shfl_xor_sync(0xffffffffu, s, 1);
                s += __shfl_xor_sync(0xffffffffu, s, 2);
                sums[mf][r][cls] = s;
            }
    if (tig == 0) {
        #pragma unroll
        for (int mf = 0; mf < 4; mf++)
            #pragma unroll
            for (int r = 0; r < 2; r++) {
                int row = wm + mf * 16 + gid + r * 8;
                psum[(w >> 1) * (AQ * 2) + row * 2 + 0] = sums[mf][r][0];
                psum[(w >> 1) * (AQ * 2) + row * 2 + 1] = sums[mf][r][1];
            }
    }
    __syncthreads();

    // ---- reduce across n-warps -> invden ----
    {
        int row = tid >> 1, cls = tid & 1;
        float d = psum[0 * (AQ * 2) + row * 2 + cls]
                + psum[1 * (AQ * 2) + row * 2 + cls]
                + psum[2 * (AQ * 2) + row * 2 + cls]
                + psum[3 * (AQ * 2) + row * 2 + cls];
        invd[row * 2 + cls] = 1.f / d;
    }
    __syncthreads();

    // ---- scale by matching denominator, round to tf32, store P ----
    #pragma unroll
    for (int mf = 0; mf < 4; mf++) {
        int r0 = wm + mf * 16 + gid;
        int r1 = r0 + 8;
        float i0c = invd[r0 * 2], i0i = invd[r0 * 2 + 1];
        float i1c = invd[r1 * 2], i1i = invd[r1 * 2 + 1];
        #pragma unroll
        for (int nf = 0; nf < 4; nf++) {
            int col0 = wn + nf * 8 + tig * 2;
            bool c0 = (col0 < T_), c1 = (col0 + 1 < T_);
            float2 p0, p1;
            p0.x = roundtf(sacc[mf][nf][0] * (c0 ? i0c : i0i));
            p0.y = roundtf(sacc[mf][nf][1] * (c1 ? i0c : i0i));
            p1.x = roundtf(sacc[mf][nf][2] * (c0 ? i1c : i1i));
            p1.y = roundtf(sacc[mf][nf][3] * (c1 ? i1c : i1i));
            *(float2*)&P[r0 * PLD + col0] = p0;
            *(float2*)&P[r1 * PLD + col0] = p1;
        }
    }
    __syncthreads();

    // ---- PV GEMM: O[128 q][64 d] = P[128x128] x Vt^T ; warp grid 4(m) x 2(n)
    const int pm = (w & 3) * 32;
    const int pn = (w >> 2) * 32;
    const uint32_t* Pu  = (const uint32_t*)P;
    const uint32_t* Vtu = (const uint32_t*)Vt;

    float pacc[2][4][4];
    #pragma unroll
    for (int mf = 0; mf < 2; mf++)
        #pragma unroll
        for (int nf = 0; nf < 4; nf++)
            #pragma unroll
            for (int r = 0; r < 4; r++) pacc[mf][nf][r] = 0.f;

    #pragma unroll
    for (int kk = 0; kk < NK; kk += 8) {
        uint32_t a[2][4], bf[4][2];
        #pragma unroll
        for (int mf = 0; mf < 2; mf++) {
            int mb2 = pm + mf * 16;
            a[mf][0] = Pu[(mb2 + gid)     * PLD + kk + tig];
            a[mf][1] = Pu[(mb2 + gid + 8) * PLD + kk + tig];
            a[mf][2] = Pu[(mb2 + gid)     * PLD + kk + tig + 4];
            a[mf][3] = Pu[(mb2 + gid + 8) * PLD + kk + tig + 4];
        }
        #pragma unroll
        for (int nf = 0; nf < 4; nf++) {
            int nb = pn + nf * 8;
            bf[nf][0] = Vtu[(nb + gid) * PLD + kk + tig];
            bf[nf][1] = Vtu[(nb + gid) * PLD + kk + tig + 4];
        }
        #pragma unroll
        for (int mf = 0; mf < 2; mf++)
            #pragma unroll
            for (int nf = 0; nf < 4; nf++)
                mma_tf32(pacc[mf][nf], a[mf], bf[nf]);
    }

    // ---- epilogue: store combined output (pre-rounded for O-GEMM) ----
    #pragma unroll
    for (int mf = 0; mf < 2; mf++) {
        int r0 = pm + mf * 16 + gid;
        int r1 = r0 + 8;
        #pragma unroll
        for (int nf = 0; nf < 4; nf++) {
            int dc = pn + nf * 8 + tig * 2;
            float2 o0, o1;
            o0.x = roundtf(pacc[mf][nf][0]); o0.y = roundtf(pacc[mf][nf][1]);
            o1.x = roundtf(pacc[mf][nf][2]); o1.y = roundtf(pacc[mf][nf][3]);
            *(float2*)(out + ((size_t)b * S_ + s0 + r0) * C_ + h * D_ + dc) = o0;
            *(float2*)(out + ((size_t)b * S_ + s0 + r1) * C_ + h * D_ + dc) = o1;
        }
    }
}

// ---------------------------------------------------------------------------
// launch
// ---------------------------------------------------------------------------
extern "C" void kernel_launch(void* const* d_in, const int* in_sizes, int n_in,
                              void* d_out, int out_size)
{
    const float* hidden = (const float*)d_in[0];
    const float* enc    = (const float*)d_in[1];
    const float* idemb  = (const float*)d_in[2];
    const float* Wq     = (const float*)d_in[3];
    const float* Wk     = (const float*)d_in[4];
    const float* Wv     = (const float*)d_in[5];
    const float* Wik    = (const float*)d_in[6];
    const float* Wiv    = (const float*)d_in[7];
    const float* Wo     = (const float*)d_in[8];
    const float* bo     = (const float*)d_in[9];
    float* out          = (float*)d_out;

    float *q, *k, *v, *ik, *iv, *comb;
    float *hid_t, *enc_t, *id_t, *wq_t, *wk_t, *wv_t, *wik_t, *wiv_t, *wo_t;
    cudaGetSymbolAddress((void**)&q,     g_q);
    cudaGetSymbolAddress((void**)&k,     g_k);
    cudaGetSymbolAddress((void**)&v,     g_v);
    cudaGetSymbolAddress((void**)&ik,    g_ik);
    cudaGetSymbolAddress((void**)&iv,    g_iv);
    cudaGetSymbolAddress((void**)&comb,  g_comb);
    cudaGetSymbolAddress((void**)&hid_t, g_hid_t);
    cudaGetSymbolAddress((void**)&enc_t, g_enc_t);
    cudaGetSymbolAddress((void**)&id_t,  g_idt);
    cudaGetSymbolAddress((void**)&wq_t,  g_wq_t);
    cudaGetSymbolAddress((void**)&wk_t,  g_wk_t);
    cudaGetSymbolAddress((void**)&wv_t,  g_wv_t);
    cudaGetSymbolAddress((void**)&wik_t, g_wik_t);
    cudaGetSymbolAddress((void**)&wiv_t, g_wiv_t);
    cudaGetSymbolAddress((void**)&wo_t,  g_wo_t);

    cudaFuncSetAttribute(gemm_main,
                         cudaFuncAttributeMaxDynamicSharedMemorySize, GEMM_SMEM_BYTES);
    cudaFuncSetAttribute(gemm_epi,
                         cudaFuncAttributeMaxDynamicSharedMemorySize, GEMM_SMEM_BYTES);
    cudaFuncSetAttribute(attn_kernel,
                         cudaFuncAttributeMaxDynamicSharedMemorySize, ATTN_SMEM_BYTES);

    // pre-round all GEMM operands to tf32
    dim3 rgrid(1024, 9);
    round_multi<<<rgrid, 256>>>(hidden, enc, idemb, Wq, Wk, Wv, Wik, Wiv, Wo,
                                hid_t, enc_t, id_t, wq_t, wk_t, wv_t,
                                wik_t, wiv_t, wo_t);

    // Q projection + all K/V projections in one launch (KV first)
    dim3 gmain(C_ / GBN, 136);
    gemm_main<<<gmain, GT, GEMM_SMEM_BYTES>>>(hid_t, wq_t, q,
                                              enc_t, id_t, wk_t, wv_t, wik_t, wiv_t,
                                              k, v, ik, iv);

    // tensor-core dual attention -> combined [B,S,C] (pre-rounded)
    dim3 agrid(S_ / AQ, B_ * H_);
    attn_kernel<<<agrid, 256, ATTN_SMEM_BYTES>>>(q, k, v, ik, iv, comb);

    // output projection + bias + residual
    dim3 gepi(C_ / GBN, M_BIG / GBM);
    gemm_epi<<<gepi, GT, GEMM_SMEM_BYTES>>>(comb, wo_t, out, bo, hidden);
}

// round 16
// speedup vs baseline: 1.1366x; 1.1366x over previous
#include <cuda_runtime.h>
#include <cstdint>
#include <cstdio>

// ---------------------------------------------------------------------------
// Problem constants
// ---------------------------------------------------------------------------
#define B_    4
#define S_    4096
#define C_    1280
#define X_    2048
#define T_    77
#define LID_  32
#define H_    20
#define D_    64

#define M_BIG (B_ * S_)        // 16384

// ---------------------------------------------------------------------------
// Scratch (no allocations allowed -> __device__ globals)
// ---------------------------------------------------------------------------
__device__ float g_q   [(size_t)M_BIG * C_];
__device__ float g_comb[(size_t)M_BIG * C_];     // pre-rounded to tf32
__device__ float g_k [B_ * T_   * C_];
__device__ float g_v [B_ * T_   * C_];
__device__ float g_ik[B_ * LID_ * C_];
__device__ float g_iv[B_ * LID_ * C_];

// tf32-pre-rounded operand copies
__device__ float g_hid_t[(size_t)M_BIG * C_];
__device__ float g_enc_t[B_ * T_   * X_];
__device__ float g_idt  [B_ * LID_ * X_];
__device__ float g_wq_t [C_ * C_];
__device__ float g_wk_t [C_ * X_];
__device__ float g_wv_t [C_ * X_];
__device__ float g_wik_t[C_ * X_];
__device__ float g_wiv_t[C_ * X_];
__device__ float g_wo_t [C_ * C_];

__device__ __forceinline__ uint32_t f2tf32(float x) {
    uint32_t r;
    asm("cvt.rna.tf32.f32 %0, %1;" : "=r"(r) : "f"(x));
    return r;
}
__device__ __forceinline__ float roundtf(float x) {
    return __uint_as_float(f2tf32(x));
}

// ---------------------------------------------------------------------------
// Pre-round pass
// ---------------------------------------------------------------------------
__global__ __launch_bounds__(256)
void round_multi(const float* __restrict__ hidden, const float* __restrict__ enc,
                 const float* __restrict__ idemb,
                 const float* __restrict__ Wq, const float* __restrict__ Wk,
                 const float* __restrict__ Wv, const float* __restrict__ Wik,
                 const float* __restrict__ Wiv, const float* __restrict__ Wo,
                 float* hid_t, float* enc_t, float* id_t,
                 float* wq_t, float* wk_t, float* wv_t,
                 float* wik_t, float* wiv_t, float* wo_t)
{
    const float* src; float* dst; size_t n;
    switch (blockIdx.y) {
        case 0: src = hidden; dst = hid_t; n = (size_t)M_BIG * C_;   break;
        case 1: src = enc;    dst = enc_t; n = (size_t)B_ * T_ * X_; break;
        case 2: src = idemb;  dst = id_t;  n = (size_t)B_ * LID_ * X_; break;
        case 3: src = Wq;     dst = wq_t;  n = (size_t)C_ * C_;      break;
        case 4: src = Wk;     dst = wk_t;  n = (size_t)C_ * X_;      break;
        case 5: src = Wv;     dst = wv_t;  n = (size_t)C_ * X_;      break;
        case 6: src = Wik;    dst = wik_t; n = (size_t)C_ * X_;      break;
        case 7: src = Wiv;    dst = wiv_t; n = (size_t)C_ * X_;      break;
        default:src = Wo;     dst = wo_t;  n = (size_t)C_ * C_;      break;
    }
    size_t n4 = n >> 2;
    size_t stride = (size_t)gridDim.x * blockDim.x;
    for (size_t i = (size_t)blockIdx.x * blockDim.x + threadIdx.x; i < n4; i += stride) {
        float4 v = ((const float4*)src)[i];
        v.x = roundtf(v.x); v.y = roundtf(v.y);
        v.z = roundtf(v.z); v.w = roundtf(v.w);
        ((float4*)dst)[i] = v;
    }
}

// ---------------------------------------------------------------------------
// cp.async helpers
// ---------------------------------------------------------------------------
__device__ __forceinline__ void cp_async16(uint32_t dst, const void* src) {
    asm volatile("cp.async.cg.shared.global [%0], [%1], 16;\n"
                 :: "r"(dst), "l"(src));
}
__device__ __forceinline__ void cp_commit() {
    asm volatile("cp.async.commit_group;\n");
}
template <int N>
__device__ __forceinline__ void cp_wait() {
    asm volatile("cp.async.wait_group %0;\n" :: "n"(N));
}

__device__ __forceinline__ void mma_tf32(float* c, const uint32_t* a, const uint32_t* b) {
    asm volatile(
        "mma.sync.aligned.m16n8k8.row.col.f32.tf32.tf32.f32 "
        "{%0,%1,%2,%3}, {%4,%5,%6,%7}, {%8,%9}, {%0,%1,%2,%3};\n"
        : "+f"(c[0]), "+f"(c[1]), "+f"(c[2]), "+f"(c[3])
        : "r"(a[0]), "r"(a[1]), "r"(a[2]), "r"(a[3]),
          "r"(b[0]), "r"(b[1]));
}

// ---------------------------------------------------------------------------
// mma.sync tf32 GEMM (NT): C[m,n] = sum_k A[m,k]*B[n,k]
// R12/R14 configuration: block 128x128, BK=32, 4 warps (warp tile 64x64),
// GLD=36 padded smem, 3-stage cp.async, 2 CTAs/SM.
// ---------------------------------------------------------------------------
#define GT   128                    // threads per block
#define GBM 128
#define GBN 128
#define GBK 32
#define GLD 36
#define ASZ (GBM * GLD)
#define BSZ (GBN * GLD)
#define STG (ASZ + BSZ)
#define NSTG 3
#define GEMM_SMEM_BYTES (NSTG * STG * 4)     // 110592 (x2 CTAs = 221184 <= 228KB)

template <bool EPI, bool CLAMP>
__device__ __forceinline__
void gemm_body(const float* __restrict__ A, const float* __restrict__ Bm,
               float* __restrict__ C, int M, int K, int row0, int col0,
               const float* __restrict__ bias, const float* __restrict__ residual,
               float* smem)
{
    const int tid  = threadIdx.x;
    const int lane = tid & 31;
    const int w    = tid >> 5;
    const int gid  = lane >> 2;
    const int tig  = lane & 3;
    const int wm   = (w & 1) * 64;
    const int wn   = (w >> 1) * 64;

    uint32_t smem_u32 = (uint32_t)__cvta_generic_to_shared(smem);

    float acc[4][8][4];
    #pragma unroll
    for (int mf = 0; mf < 4; mf++)
        #pragma unroll
        for (int nf = 0; nf < 8; nf++)
            #pragma unroll
            for (int r = 0; r < 4; r++) acc[mf][nf][r] = 0.f;

    const int niter = K / GBK;

    auto load_tile = [&](int kt, int st) {
        const int k0 = kt * GBK;
        uint32_t abase = smem_u32 + (uint32_t)(st * STG) * 4u;
        uint32_t bbase = abase + (uint32_t)ASZ * 4u;
        #pragma unroll
        for (int i = 0; i < 8; i++) {
            int idx = tid + i * GT;
            int m   = idx >> 3;
            int k4  = idx & 7;
            int gr  = row0 + m;
            if (CLAMP) { if (gr > M - 1) gr = M - 1; }
            cp_async16(abase + (uint32_t)(m * GLD + k4 * 4) * 4u,
                       A + (size_t)gr * K + k0 + k4 * 4);
        }
        #pragma unroll
        for (int i = 0; i < 8; i++) {
            int idx = tid + i * GT;
            int n   = idx >> 3;
            int k4  = idx & 7;
            cp_async16(bbase + (uint32_t)(n * GLD + k4 * 4) * 4u,
                       Bm + (size_t)(col0 + n) * K + k0 + k4 * 4);
        }
        cp_commit();
    };

    load_tile(0, 0);
    load_tile(1, 1);

    for (int it = 0; it < niter; ++it) {
        if (it + 1 < niter) cp_wait<1>(); else cp_wait<0>();
        __syncthreads();
        if (it + 2 < niter) load_tile(it + 2, (it + 2) % NSTG);

        const uint32_t* As = (const uint32_t*)(smem + (it % NSTG) * STG);
        const uint32_t* Bs = As + ASZ;

        #pragma unroll
        for (int kk = 0; kk < GBK; kk += 8) {
            uint32_t a[4][4], bf[8][2];
            #pragma unroll
            for (int mf = 0; mf < 4; mf++) {
                int mb2 = wm + mf * 16;
                a[mf][0] = As[(mb2 + gid)     * GLD + kk + tig];
                a[mf][1] = As[(mb2 + gid + 8) * GLD + kk + tig];
                a[mf][2] = As[(mb2 + gid)     * GLD + kk + tig + 4];
                a[mf][3] = As[(mb2 + gid + 8) * GLD + kk + tig + 4];
            }
            #pragma unroll
            for (int nf = 0; nf < 8; nf++) {
                int nb = wn + nf * 8;
                bf[nf][0] = Bs[(nb + gid) * GLD + kk + tig];
                bf[nf][1] = Bs[(nb + gid) * GLD + kk + tig + 4];
            }
            #pragma unroll
            for (int mf = 0; mf < 4; mf++)
                #pragma unroll
                for (int nf = 0; nf < 8; nf++)
                    mma_tf32(acc[mf][nf], a[mf], bf[nf]);
        }
    }

    #pragma unroll
    for (int mf = 0; mf < 4; mf++) {
        int r0g = row0 + wm + mf * 16 + gid;
        int r1g = r0g + 8;
        #pragma unroll
        for (int nf = 0; nf < 8; nf++) {
            int gc = col0 + wn + nf * 8 + tig * 2;
            float2 v0 = make_float2(acc[mf][nf][0], acc[mf][nf][1]);
            float2 v1 = make_float2(acc[mf][nf][2], acc[mf][nf][3]);
            if (EPI) {
                float2 bb = *(const float2*)(bias + gc);
                v0.x += bb.x; v0.y += bb.y;
                v1.x += bb.x; v1.y += bb.y;
            }
            if (r0g < M) {
                if (EPI) {
                    float2 rr = *(const float2*)(residual + (size_t)r0g * C_ + gc);
                    v0.x += rr.x; v0.y += rr.y;
                }
                *(float2*)(C + (size_t)r0g * C_ + gc) = v0;
            }
            if (r1g < M) {
                if (EPI) {
                    float2 rr = *(const float2*)(residual + (size_t)r1g * C_ + gc);
                    v1.x += rr.x; v1.y += rr.y;
                }
                *(float2*)(C + (size_t)r1g * C_ + gc) = v1;
            }
        }
    }
}

// Q projection + all four K/V projections in ONE launch. grid (10, 136).
// KV blocks (K=2048, 1.6x longer) scheduled FIRST to avoid a long tail.
__global__ __launch_bounds__(GT, 2)
void gemm_main(const float* __restrict__ hid, const float* __restrict__ wq,
               float* __restrict__ q,
               const float* __restrict__ enc, const float* __restrict__ idemb,
               const float* __restrict__ wk,  const float* __restrict__ wv,
               const float* __restrict__ wik, const float* __restrict__ wiv,
               float* __restrict__ k, float* __restrict__ v,
               float* __restrict__ ik, float* __restrict__ iv)
{
    extern __shared__ float dynsm[];
    const int y = blockIdx.y;
    const int col0 = blockIdx.x * GBN;
    if (y >= 8) {
        gemm_body<false, false>(hid, wq, q, M_BIG, C_, (y - 8) * GBM, col0,
                                nullptr, nullptr, dynsm);
        return;
    }
    const int z = y;
    const float* A; const float* Bm; float* Cp; int M; int row0;
    if (z < 3)       { A = enc;   Bm = wk;  Cp = k;  M = B_ * T_;   row0 = z * GBM; }
    else if (z < 6)  { A = enc;   Bm = wv;  Cp = v;  M = B_ * T_;   row0 = (z - 3) * GBM; }
    else if (z == 6) { A = idemb; Bm = wik; Cp = ik; M = B_ * LID_; row0 = 0; }
    else             { A = idemb; Bm = wiv; Cp = iv; M = B_ * LID_; row0 = 0; }
    gemm_body<false, true>(A, Bm, Cp, M, X_, row0, col0, nullptr, nullptr, dynsm);
}

// O projection + bias + residual. grid (10, 128).
__global__ __launch_bounds__(GT, 2)
void gemm_epi(const float* __restrict__ A, const float* __restrict__ W,
              float* __restrict__ C,
              const float* __restrict__ bias, const float* __restrict__ residual)
{
    extern __shared__ float dynsm[];
    gemm_body<true, false>(A, W, C, M_BIG, C_, blockIdx.y * GBM,
                           blockIdx.x * GBN, bias, residual, dynsm);
}

// ---------------------------------------------------------------------------
// Tensor-core attention (tf32 mma), 2 CTAs/SM via smem aliasing.
// Per CTA: 128 queries x one (b,h). Combined key axis 128:
//   cols 0..76   = cross keys (K, V)
//   cols 77..108 = id keys   (idK, idV)
//   cols 109..127 = padding (e forced to 0)
// P tile ALIASES the Qs/Ks region (written only after the score GEMM has
// consumed Qs/Ks, separated by two __syncthreads).
// ---------------------------------------------------------------------------
#define AQ   128                    // queries per CTA
#define NK   128                    // padded key axis
#define NKR  109                    // real keys (77 cross + 32 id)
#define QLD  68                     // Qs/Ks row stride (64 + 4)
#define PLD  132                    // P/Vt key-dim stride (128 + 4)

#define SM_QS  (AQ * QLD)           // 8704
#define SM_KS  (NK * QLD)           // 8704
#define SM_P   (AQ * PLD)           // 16896 (aliases Qs+Ks = 17408)
#define SM_AL  (SM_QS + SM_KS)      // 17408 alias region
#define SM_VT  (D_ * PLD)           // 8448
#define SM_PS  (4 * AQ * 2)         // 1024 (psum[nwarp][row][cls])
#define SM_ID  (AQ * 2)             // 256  (invden[row][cls])
#define ATTN_SMEM_FLOATS (SM_AL + SM_VT + SM_PS + SM_ID)
#define ATTN_SMEM_BYTES  (ATTN_SMEM_FLOATS * 4)   // 108544 (x2 = 217088 <= 228KB)

__global__ __launch_bounds__(256, 2)
void attn_kernel(const float* __restrict__ q,
                 const float* __restrict__ kbuf, const float* __restrict__ vbuf,
                 const float* __restrict__ ikbuf, const float* __restrict__ ivbuf,
                 float* __restrict__ out)
{
    extern __shared__ float sm[];
    float* Qs   = sm;                  // [0, 8704)
    float* Ks   = Qs + SM_QS;          // [8704, 17408)
    float* P    = sm;                  // ALIAS over Qs+Ks
    float* Vt   = sm + SM_AL;          // [17408, 25856)
    float* psum = Vt + SM_VT;          // [25856, 26880)
    float* invd = psum + SM_PS;        // [26880, 27136)

    const int bh = blockIdx.y;
    const int b = bh / H_, h = bh % H_;
    const int s0 = blockIdx.x * AQ;
    const int tid = threadIdx.x, lane = tid & 31, w = tid >> 5;
    const int gid = lane >> 2, tig = lane & 3;
    const float scale = 0.125f;

    // ---- stage: Q (rounded) ----
    for (int idx = tid; idx < AQ * 16; idx += 256) {
        int r = idx >> 4, d4 = (idx & 15) << 2;
        float4 g = *(const float4*)(q + ((size_t)b * S_ + s0 + r) * C_ + h * D_ + d4);
        float* dst = Qs + r * QLD + d4;
        dst[0] = roundtf(g.x); dst[1] = roundtf(g.y);
        dst[2] = roundtf(g.z); dst[3] = roundtf(g.w);
    }
    // ---- stage: K rows 0..76 (cross), 77..108 (id) ----
    for (int idx = tid; idx < T_ * 16; idx += 256) {
        int r = idx >> 4, d4 = (idx & 15) << 2;
        float4 g = *(const float4*)(kbuf + ((size_t)b * T_ + r) * C_ + h * D_ + d4);
        float* dst = Ks + r * QLD + d4;
        dst[0] = roundtf(g.x); dst[1] = roundtf(g.y);
        dst[2] = roundtf(g.z); dst[3] = roundtf(g.w);
    }
    for (int idx = tid; idx < LID_ * 16; idx += 256) {
        int r = idx >> 4, d4 = (idx & 15) << 2;
        float4 g = *(const float4*)(ikbuf + ((size_t)b * LID_ + r) * C_ + h * D_ + d4);
        float* dst = Ks + (T_ + r) * QLD + d4;
        dst[0] = roundtf(g.x); dst[1] = roundtf(g.y);
        dst[2] = roundtf(g.z); dst[3] = roundtf(g.w);
    }
    // ---- stage: Vt (transposed, zero-padded key cols) ----
    for (int idx = tid; idx < SM_VT; idx += 256) Vt[idx] = 0.f;
    __syncthreads();   // zeros visible before transpose-fill
    for (int idx = tid; idx < T_ * 16; idx += 256) {
        int r = idx >> 4, d4 = (idx & 15) << 2;
        float4 g = *(const float4*)(vbuf + ((size_t)b * T_ + r) * C_ + h * D_ + d4);
        Vt[(d4 + 0) * PLD + r] = roundtf(g.x);
        Vt[(d4 + 1) * PLD + r] = roundtf(g.y);
        Vt[(d4 + 2) * PLD + r] = roundtf(g.z);
        Vt[(d4 + 3) * PLD + r] = roundtf(g.w);
    }
    for (int idx = tid; idx < LID_ * 16; idx += 256) {
        int r = idx >> 4, d4 = (idx & 15) << 2;
        float4 g = *(const float4*)(ivbuf + ((size_t)b * LID_ + r) * C_ + h * D_ + d4);
        Vt[(d4 + 0) * PLD + T_ + r] = roundtf(g.x);
        Vt[(d4 + 1) * PLD + T_ + r] = roundtf(g.y);
        Vt[(d4 + 2) * PLD + T_ + r] = roundtf(g.z);
        Vt[(d4 + 3) * PLD + T_ + r] = roundtf(g.w);
    }
    __syncthreads();

    // ---- score GEMM: S[128 q][128 key] ; warp grid 2(m) x 4(n) ----
    const int wm = (w & 1) * 64;
    const int wn = (w >> 1) * 32;
    const uint32_t* Qu = (const uint32_t*)Qs;
    const uint32_t* Ku = (const uint32_t*)Ks;

    float sacc[4][4][4];
    #pragma unroll
    for (int mf = 0; mf < 4; mf++)
        #pragma unroll
        for (int nf = 0; nf < 4; nf++)
            #pragma unroll
            for (int r = 0; r < 4; r++) sacc[mf][nf][r] = 0.f;

    #pragma unroll
    for (int kk = 0; kk < D_; kk += 8) {
        uint32_t a[4][4], bf[4][2];
        #pragma unroll
        for (int mf = 0; mf < 4; mf++) {
            int mb2 = wm + mf * 16;
            a[mf][0] = Qu[(mb2 + gid)     * QLD + kk + tig];
            a[mf][1] = Qu[(mb2 + gid + 8) * QLD + kk + tig];
            a[mf][2] = Qu[(mb2 + gid)     * QLD + kk + tig + 4];
            a[mf][3] = Qu[(mb2 + gid + 8) * QLD + kk + tig + 4];
        }
        #pragma unroll
        for (int nf = 0; nf < 4; nf++) {
            int nb = wn + nf * 8;
            bf[nf][0] = Ku[(nb + gid) * QLD + kk + tig];
            bf[nf][1] = Ku[(nb + gid) * QLD + kk + tig + 4];
        }
        #pragma unroll
        for (int mf = 0; mf < 4; mf++)
            #pragma unroll
            for (int nf = 0; nf < 4; nf++)
                mma_tf32(sacc[mf][nf], a[mf], bf[nf]);
    }

    // ---- exp + per-class row sums (no max shift; scores O(1)) ----
    float sums[4][2][2];
    #pragma unroll
    for (int mf = 0; mf < 4; mf++)
        #pragma unroll
        for (int r = 0; r < 2; r++) { sums[mf][r][0] = 0.f; sums[mf][r][1] = 0.f; }

    #pragma unroll
    for (int mf = 0; mf < 4; mf++)
        #pragma unroll
        for (int nf = 0; nf < 4; nf++) {
            int col0 = wn + nf * 8 + tig * 2;
            int col1 = col0 + 1;
            #pragma unroll
            for (int r = 0; r < 2; r++) {
                float e0 = (col0 < NKR) ? __expf(sacc[mf][nf][r * 2 + 0] * scale) : 0.f;
                float e1 = (col1 < NKR) ? __expf(sacc[mf][nf][r * 2 + 1] * scale) : 0.f;
                if (col0 < T_) sums[mf][r][0] += e0; else sums[mf][r][1] += e0;
                if (col1 < T_) sums[mf][r][0] += e1; else sums[mf][r][1] += e1;
                sacc[mf][nf][r * 2 + 0] = e0;
                sacc[mf][nf][r * 2 + 1] = e1;
            }
        }

    // quad-reduce (tig lanes share rows) and publish partials
    #pragma unroll
    for (int mf = 0; mf < 4; mf++)
        #pragma unroll
        for (int r = 0; r < 2; r++)
            #pragma unroll
            for (int cls = 0; cls < 2; cls++) {
                float s = sums[mf][r][cls];
                s += __shfl_xor_sync(0xffffffffu, s, 1);
                s += __shfl_xor_sync(0xffffffffu, s, 2);
                sums[mf][r][cls] = s;
            }
    if (tig == 0) {
        #pragma unroll
        for (int mf = 0; mf < 4; mf++)
            #pragma unroll
            for (int r = 0; r < 2; r++) {
                int row = wm + mf * 16 + gid + r * 8;
                psum[(w >> 1) * (AQ * 2) + row * 2 + 0] = sums[mf][r][0];
                psum[(w >> 1) * (AQ * 2) + row * 2 + 1] = sums[mf][r][1];
            }
    }
    __syncthreads();

    // ---- reduce across n-warps -> invden ----
    {
        int row = tid >> 1, cls = tid & 1;
        float d = psum[0 * (AQ * 2) + row * 2 + cls]
                + psum[1 * (AQ * 2) + row * 2 + cls]
                + psum[2 * (AQ * 2) + row * 2 + cls]
                + psum[3 * (AQ * 2) + row * 2 + cls];
        invd[row * 2 + cls] = 1.f / d;
    }
    __syncthreads();   // all score-GEMM reads of Qs/Ks complete; P may now alias

    // ---- scale by matching denominator, round to tf32, store P ----
    #pragma unroll
    for (int mf = 0; mf < 4; mf++) {
        int r0 = wm + mf * 16 + gid;
        int r1 = r0 + 8;
        float i0c = invd[r0 * 2], i0i = invd[r0 * 2 + 1];
        float i1c = invd[r1 * 2], i1i = invd[r1 * 2 + 1];
        #pragma unroll
        for (int nf = 0; nf < 4; nf++) {
            int col0 = wn + nf * 8 + tig * 2;
            bool c0 = (col0 < T_), c1 = (col0 + 1 < T_);
            float2 p0, p1;
            p0.x = roundtf(sacc[mf][nf][0] * (c0 ? i0c : i0i));
            p0.y = roundtf(sacc[mf][nf][1] * (c1 ? i0c : i0i));
            p1.x = roundtf(sacc[mf][nf][2] * (c0 ? i1c : i1i));
            p1.y = roundtf(sacc[mf][nf][3] * (c1 ? i1c : i1i));
            *(float2*)&P[r0 * PLD + col0] = p0;
            *(float2*)&P[r1 * PLD + col0] = p1;
        }
    }
    __syncthreads();

    // ---- PV GEMM: O[128 q][64 d] = P[128x128] x Vt^T ; warp grid 4(m) x 2(n)
    const int pm = (w & 3) * 32;
    const int pn = (w >> 2) * 32;
    const uint32_t* Pu  = (const uint32_t*)P;
    const uint32_t* Vtu = (const uint32_t*)Vt;

    float pacc[2][4][4];
    #pragma unroll
    for (int mf = 0; mf < 2; mf++)
        #pragma unroll
        for (int nf = 0; nf < 4; nf++)
            #pragma unroll
            for (int r = 0; r < 4; r++) pacc[mf][nf][r] = 0.f;

    #pragma unroll
    for (int kk = 0; kk < NK; kk += 8) {
        uint32_t a[2][4], bf[4][2];
        #pragma unroll
        for (int mf = 0; mf < 2; mf++) {
            int mb2 = pm + mf * 16;
            a[mf][0] = Pu[(mb2 + gid)     * PLD + kk + tig];
            a[mf][1] = Pu[(mb2 + gid + 8) * PLD + kk + tig];
            a[mf][2] = Pu[(mb2 + gid)     * PLD + kk + tig + 4];
            a[mf][3] = Pu[(mb2 + gid + 8) * PLD + kk + tig + 4];
        }
        #pragma unroll
        for (int nf = 0; nf < 4; nf++) {
            int nb = pn + nf * 8;
            bf[nf][0] = Vtu[(nb + gid) * PLD + kk + tig];
            bf[nf][1] = Vtu[(nb + gid) * PLD + kk + tig + 4];
        }
        #pragma unroll
        for (int mf = 0; mf < 2; mf++)
            #pragma unroll
            for (int nf = 0; nf < 4; nf++)
                mma_tf32(pacc[mf][nf], a[mf], bf[nf]);
    }

    // ---- epilogue: store combined output (pre-rounded for O-GEMM) ----
    #pragma unroll
    for (int mf = 0; mf < 2; mf++) {
        int r0 = pm + mf * 16 + gid;
        int r1 = r0 + 8;
        #pragma unroll
        for (int nf = 0; nf < 4; nf++) {
            int dc = pn + nf * 8 + tig * 2;
            float2 o0, o1;
            o0.x = roundtf(pacc[mf][nf][0]); o0.y = roundtf(pacc[mf][nf][1]);
            o1.x = roundtf(pacc[mf][nf][2]); o1.y = roundtf(pacc[mf][nf][3]);
            *(float2*)(out + ((size_t)b * S_ + s0 + r0) * C_ + h * D_ + dc) = o0;
            *(float2*)(out + ((size_t)b * S_ + s0 + r1) * C_ + h * D_ + dc) = o1;
        }
    }
}

// ---------------------------------------------------------------------------
// launch
// ---------------------------------------------------------------------------
extern "C" void kernel_launch(void* const* d_in, const int* in_sizes, int n_in,
                              void* d_out, int out_size)
{
    const float* hidden = (const float*)d_in[0];
    const float* enc    = (const float*)d_in[1];
    const float* idemb  = (const float*)d_in[2];
    const float* Wq     = (const float*)d_in[3];
    const float* Wk     = (const float*)d_in[4];
    const float* Wv     = (const float*)d_in[5];
    const float* Wik    = (const float*)d_in[6];
    const float* Wiv    = (const float*)d_in[7];
    const float* Wo     = (const float*)d_in[8];
    const float* bo     = (const float*)d_in[9];
    float* out          = (float*)d_out;

    float *q, *k, *v, *ik, *iv, *comb;
    float *hid_t, *enc_t, *id_t, *wq_t, *wk_t, *wv_t, *wik_t, *wiv_t, *wo_t;
    cudaGetSymbolAddress((void**)&q,     g_q);
    cudaGetSymbolAddress((void**)&k,     g_k);
    cudaGetSymbolAddress((void**)&v,     g_v);
    cudaGetSymbolAddress((void**)&ik,    g_ik);
    cudaGetSymbolAddress((void**)&iv,    g_iv);
    cudaGetSymbolAddress((void**)&comb,  g_comb);
    cudaGetSymbolAddress((void**)&hid_t, g_hid_t);
    cudaGetSymbolAddress((void**)&enc_t, g_enc_t);
    cudaGetSymbolAddress((void**)&id_t,  g_idt);
    cudaGetSymbolAddress((void**)&wq_t,  g_wq_t);
    cudaGetSymbolAddress((void**)&wk_t,  g_wk_t);
    cudaGetSymbolAddress((void**)&wv_t,  g_wv_t);
    cudaGetSymbolAddress((void**)&wik_t, g_wik_t);
    cudaGetSymbolAddress((void**)&wiv_t, g_wiv_t);
    cudaGetSymbolAddress((void**)&wo_t,  g_wo_t);

    cudaFuncSetAttribute(gemm_main,
                         cudaFuncAttributeMaxDynamicSharedMemorySize, GEMM_SMEM_BYTES);
    cudaFuncSetAttribute(gemm_epi,
                         cudaFuncAttributeMaxDynamicSharedMemorySize, GEMM_SMEM_BYTES);
    cudaFuncSetAttribute(attn_kernel,
                         cudaFuncAttributeMaxDynamicSharedMemorySize, ATTN_SMEM_BYTES);

    // pre-round all GEMM operands to tf32
    dim3 rgrid(1024, 9);
    round_multi<<<rgrid, 256>>>(hidden, enc, idemb, Wq, Wk, Wv, Wik, Wiv, Wo,
                                hid_t, enc_t, id_t, wq_t, wk_t, wv_t,
                                wik_t, wiv_t, wo_t);

    // Q projection + all K/V projections in one launch (KV first)
    dim3 gmain(C_ / GBN, 136);
    gemm_main<<<gmain, GT, GEMM_SMEM_BYTES>>>(hid_t, wq_t, q,
                                              enc_t, id_t, wk_t, wv_t, wik_t, wiv_t,
                                              k, v, ik, iv);

    // tensor-core dual attention -> combined [B,S,C] (pre-rounded)
    dim3 agrid(S_ / AQ, B_ * H_);
    attn_kernel<<<agrid, 256, ATTN_SMEM_BYTES>>>(q, k, v, ik, iv, comb);

    // output projection + bias + residual
    dim3 gepi(C_ / GBN, M_BIG / GBM);
    gemm_epi<<<gepi, GT, GEMM_SMEM_BYTES>>>(comb, wo_t, out, bo, hidden);
}